// round 15
// baseline (speedup 1.0000x reference)
#include <cuda_runtime.h>
#include <cstdint>

#define IMG_W 4096
#define IMG_H 4096
#define PX    4   // pixels per thread; 1 output row per thread (R6 structure:
                  // 31 regs / 82% occ — the only config that kept issue ~70%
                  // with headroom; 2-row tiles swelled to 40-48 regs)

// Load 6 consecutive floats (cols x0-1 .. x0+4) of row yy, zero-padded in y.
__device__ __forceinline__ void load_row6(float* n, const float* __restrict__ img,
                                          int yy, int x0, bool lft, bool rgt) {
    if ((unsigned)yy >= (unsigned)IMG_H) {
#pragma unroll
        for (int i = 0; i < 6; i++) n[i] = 0.0f;
        return;
    }
    const float* p = img + (size_t)yy * IMG_W + x0;
    float4 v = __ldg(reinterpret_cast<const float4*>(p));
    n[1] = v.x; n[2] = v.y; n[3] = v.z; n[4] = v.w;
    n[0] = lft ? __ldg(p - 1) : 0.0f;
    n[5] = rgt ? __ldg(p + PX) : 0.0f;
}

__global__ __launch_bounds__(256)
void kirsch_mask_kernel(const float* __restrict__ img, float* __restrict__ out) {
    const int x0 = (blockIdx.x * blockDim.x + threadIdx.x) * PX;
    const int y  = blockIdx.y;
    const bool lft = (x0 > 0);
    const bool rgt = (x0 + PX < IMG_W);

    // Runtime-opaque ~7 so mask+index-attach is ONE LOP3 per direction.
    const int maskReg = ~((int)(blockDim.x >> 5) - 1);   // ~7 = 0xFFFFFFF8

    float n0[6], n1[6], n2[6];
    load_row6(n0, img, y - 1, x0, lft, rgt);
    load_row6(n1, img, y,     x0, lft, rgt);
    load_row6(n2, img, y + 1, x0, lft, rgt);

    // Shared partials: top/bottom horizontal pairs, vertical column triples.
    float pt[PX + 1], pb[PX + 1], V[PX + 2];
#pragma unroll
    for (int i = 0; i < PX + 1; i++) {
        pt[i] = n0[i] + n0[i + 1];
        pb[i] = n2[i] + n2[i + 1];
    }
#pragma unroll
    for (int i = 0; i < PX + 2; i++) V[i] = n0[i] + n1[i] + n2[i];

    float code[PX];
#pragma unroll
    for (int j = 1; j <= PX; j++) {
        const float c = n0[j + 1];
        const float d = n1[j - 1];
        const float e = n1[j + 1];
        const float h = n2[j + 1];

        // Kirsch response R_k = 8*P_k - 3*T (T per-pixel const) => order by P_k.
        float P[8];
        P[0] = V[j + 1];        // c+e+h  (N)
        P[1] = pt[j] + e;       // b+c+e  (NW)
        P[2] = pt[j - 1] + c;   // a+b+c  (W)
        P[3] = pt[j - 1] + d;   // a+b+d  (SW)
        P[4] = V[j - 1];        // a+d+f  (S)
        P[5] = pb[j - 1] + d;   // d+f+g  (SE)
        P[6] = pb[j - 1] + h;   // f+g+h  (E)
        P[7] = pb[j] + e;       // e+g+h  (NE)

        // emin[di] = (bits & ~7) | di : ONE LOP3 (bits reg, maskReg, di imm).
        // Low bits clear => emin == tmp + di exactly; all P >= 0 so signed
        // int compare == float compare.
        int emin[8];
#pragma unroll
        for (int di = 0; di < 8; di++)
            emin[di] = (((int)__float_as_uint(P[di])) & maskReg) | di;

        // Min: 3-input tree (adds pre-embedded). Exact ties -> smallest di
        // (first index), matching jnp.argmin.
        int wmin = __vimin3_s32(emin[0], emin[1], emin[2]);
        int tA   = __vimin3_s32(emin[3], emin[4], emin[5]);
        int tB   = min(emin[6], emin[7]);
        wmin = __vimin3_s32(wmin, tA, tB);

        // Max: fused add+max chain; emin[di] - 2*di == tmp - di, so equal tmp
        // strictly decrease with di -> first index, matching jnp.argmax.
        int wmax = emin[0];
        wmax = __viaddmax_s32(emin[1],  -2, wmax);
        wmax = __viaddmax_s32(emin[2],  -4, wmax);
        wmax = __viaddmax_s32(emin[3],  -6, wmax);
        wmax = __viaddmax_s32(emin[4],  -8, wmax);
        wmax = __viaddmax_s32(emin[5], -10, wmax);
        wmax = __viaddmax_s32(emin[6], -12, wmax);
        wmax = __viaddmax_s32(emin[7], -14, wmax);

        // wmax = tmp_w - w (tmp_w mult of 8) => ((-wmax)<<3)&56 == 8*am.
        // code = 8*am + an; int->float via exponent-bias FADD (fma pipe).
        const unsigned s  = (0u - (unsigned)wmax) << 3;
        const unsigned cb = (s & 56u) | 0x4B000000u | ((unsigned)wmin & 7u);
        code[j - 1] = __uint_as_float(cb) - 8388608.0f;
    }

    float4* o = reinterpret_cast<float4*>(out + (size_t)y * IMG_W + x0);
    *o = make_float4(code[0], code[1], code[2], code[3]);
}

extern "C" void kernel_launch(void* const* d_in, const int* in_sizes, int n_in,
                              void* d_out, int out_size) {
    const float* img = (const float*)d_in[0];
    for (int i = 0; i < n_in; i++) {
        if (in_sizes[i] == IMG_W * IMG_H) { img = (const float*)d_in[i]; break; }
    }
    float* out = (float*)d_out;

    dim3 block(256, 1, 1);
    dim3 grid(IMG_W / (256 * PX), IMG_H, 1);  // (4, 4096)
    kirsch_mask_kernel<<<grid, block>>>(img, out);
}